// round 6
// baseline (speedup 1.0000x reference)
#include <cuda_runtime.h>
#include <cuda_bf16.h>
#include <cstdint>

#define BB 4
#define NN 4096
#define FF 32
#define KK 6
#define OO 128

#define BM 64                   // rows per CTA (4 warps x 16 rows)
#define KC 32                   // k per chunk
#define NCHUNK (NN / KC)        // 128
#define PK (KK * FF)            // 192

// ---- scratch ----
__device__ float g_bufA[BB * NN * FF];
__device__ float g_bufB[BB * NN * FF];
__device__ __nv_bfloat16 g_btg_hi[2][BB * FF * NN];
__device__ __nv_bfloat16 g_btg_lo[2][BB * FF * NN];
__device__ __nv_bfloat16 g_btp_hi[(size_t)BB * NN * PK];
__device__ __nv_bfloat16 g_btp_lo[(size_t)BB * NN * PK];
__device__ __nv_bfloat16 g_wt_hi[OO * PK];
__device__ __nv_bfloat16 g_wt_lo[OO * PK];

__device__ __forceinline__ uint32_t smem_u32(const void* p) {
    uint32_t a;
    asm("{ .reg .u64 t; cvta.to.shared.u64 t, %1; cvt.u32.u64 %0, t; }" : "=r"(a) : "l"(p));
    return a;
}
__device__ __forceinline__ void cp16(uint32_t dst, const void* src) {
    asm volatile("cp.async.cg.shared.global [%0], [%1], 16;" :: "r"(dst), "l"(src));
}
#define CP_COMMIT() asm volatile("cp.async.commit_group;" ::: "memory")
#define CP_WAIT(n)  asm volatile("cp.async.wait_group %0;" :: "n"(n) : "memory")

__device__ __forceinline__ void split2(float x, float y, uint32_t& hi, uint32_t& lo) {
    asm("cvt.rn.bf16x2.f32 %0, %1, %2;" : "=r"(hi) : "f"(y), "f"(x));
    const float h0 = __uint_as_float(hi << 16);
    const float h1 = __uint_as_float(hi & 0xFFFF0000u);
    const float l0 = x - h0;
    const float l1 = y - h1;
    asm("cvt.rn.bf16x2.f32 %0, %1, %2;" : "=r"(lo) : "f"(l1), "f"(l0));
}

__device__ __forceinline__ void mma16816(float* c,
                                         uint32_t a0, uint32_t a1, uint32_t a2, uint32_t a3,
                                         uint32_t b0, uint32_t b1) {
    asm volatile(
        "mma.sync.aligned.m16n8k16.row.col.f32.bf16.bf16.f32 "
        "{%0,%1,%2,%3}, {%4,%5,%6,%7}, {%8,%9}, {%0,%1,%2,%3};"
        : "+f"(c[0]), "+f"(c[1]), "+f"(c[2]), "+f"(c[3])
        : "r"(a0), "r"(a1), "r"(a2), "r"(a3), "r"(b0), "r"(b1));
}

// ---------------------------------------------------------------------------
// Prep x: fp32 [b][n][f] -> btg ([b][f][n] hi/lo)  +  btp slot 0
// ---------------------------------------------------------------------------
__global__ __launch_bounds__(256) void prep_b(
    const float* __restrict__ T,
    __nv_bfloat16* __restrict__ gHi,
    __nv_bfloat16* __restrict__ gLo,
    __nv_bfloat16* __restrict__ pHi,
    __nv_bfloat16* __restrict__ pLo)
{
    const int idx = blockIdx.x * 256 + threadIdx.x;
    const int n = idx & (NN - 1);
    const int f = (idx >> 12) & (FF - 1);
    const int b = idx >> 17;
    const float a = T[((size_t)b * NN + n) * FF + f];
    const __nv_bfloat16 h = __float2bfloat16_rn(a);
    const __nv_bfloat16 l = __float2bfloat16_rn(a - __bfloat162float(h));
    gHi[idx] = h;
    gLo[idx] = l;
    const size_t pidx = ((size_t)b * NN + n) * PK + f;
    pHi[pidx] = h;
    pLo[pidx] = l;
}

// ---------------------------------------------------------------------------
// Prep W': Wt[o][k6*32+f] = theta[k6] * W[k6][f][o], bf16 hi/lo
// ---------------------------------------------------------------------------
__global__ __launch_bounds__(256) void prep_w(
    const float* __restrict__ W,
    const float* __restrict__ theta,
    __nv_bfloat16* __restrict__ wHi,
    __nv_bfloat16* __restrict__ wLo)
{
    const int idx = blockIdx.x * 256 + threadIdx.x;
    const int o  = idx & (OO - 1);
    const int kf = idx >> 7;
    const int k6 = kf >> 5;
    const float v = theta[k6] * W[(size_t)kf * OO + o];
    const __nv_bfloat16 h = __float2bfloat16_rn(v);
    const size_t w = (size_t)o * PK + kf;
    wHi[w] = h;
    wLo[w] = __float2bfloat16_rn(v - __bfloat162float(h));
}

// ---------------------------------------------------------------------------
// HMMA GEMM, smem-free, barrier-free: per-warp direct-LDG pipelines.
// Tnew = alpha * L @ Tprev + beta * Tpp, plus bf16 term export.
// ---------------------------------------------------------------------------
__global__ __launch_bounds__(128, 4) void cheb_gemm_tc(
    const float* __restrict__ Lmat,
    const __nv_bfloat16* __restrict__ BtHi,
    const __nv_bfloat16* __restrict__ BtLo,
    const float* __restrict__ Tpp,
    float* __restrict__ Tnew,
    float alpha, float beta,
    __nv_bfloat16* __restrict__ outGHi,
    __nv_bfloat16* __restrict__ outGLo,
    __nv_bfloat16* __restrict__ outPHi,
    __nv_bfloat16* __restrict__ outPLo,
    int pslot)
{
    const int tid  = threadIdx.x;
    const int lane = tid & 31;
    const int wl   = tid >> 5;       // warp 0..3, owns rows wl*16..+15
    const int b    = blockIdx.y;
    const int row0 = blockIdx.x * BM;

    const int rsub = lane >> 2;      // 0..7
    const int kq   = (lane & 3) * 2; // 0,2,4,6

    // per-lane A row pointers (fp32)
    const float* a0p = Lmat + ((size_t)b * NN + row0 + wl * 16 + rsub) * NN + kq;
    const float* a1p = a0p + 8 * NN;
    // per-lane B row pointers (bf16, [f][n] layout; f = rsub + nb*8 via offset)
    const __nv_bfloat16* bhp = BtHi + ((size_t)b * FF + rsub) * NN + kq;
    const __nv_bfloat16* blp = BtLo + ((size_t)b * FF + rsub) * NN + kq;

    float2   ar[2][8];     // A raw fp32, [chunk parity][frag]: 0..3 = kb0, 4..7 = kb16
    uint32_t bb[2][16];    // B frags,   [kfrag parity][nb*4 + {h0,h1,l0,l1}]
    float acc[4][4];
#pragma unroll
    for (int i = 0; i < 4; i++)
#pragma unroll
        for (int j = 0; j < 4; j++) acc[i][j] = 0.0f;

#define LOAD_A(c, ib) do {                                        \
        const float* _p0 = a0p + (c) * KC;                        \
        const float* _p1 = a1p + (c) * KC;                        \
        ar[ib][0] = __ldcs((const float2*)(_p0));                 \
        ar[ib][1] = __ldcs((const float2*)(_p1));                 \
        ar[ib][2] = __ldcs((const float2*)(_p0 + 8));             \
        ar[ib][3] = __ldcs((const float2*)(_p1 + 8));             \
        ar[ib][4] = __ldcs((const float2*)(_p0 + 16));            \
        ar[ib][5] = __ldcs((const float2*)(_p1 + 16));            \
        ar[ib][6] = __ldcs((const float2*)(_p0 + 24));            \
        ar[ib][7] = __ldcs((const float2*)(_p1 + 24));            \
    } while (0)

#define LOAD_B(g, ib) do {                                                        \
        const int _off = (g) * 16;                                                \
        _Pragma("unroll")                                                         \
        for (int _nb = 0; _nb < 4; _nb++) {                                       \
            const size_t _ro = (size_t)_nb * 8 * NN + _off;                       \
            bb[ib][_nb*4+0] = __ldg((const uint32_t*)(bhp + _ro));                \
            bb[ib][_nb*4+1] = __ldg((const uint32_t*)(bhp + _ro + 8));            \
            bb[ib][_nb*4+2] = __ldg((const uint32_t*)(blp + _ro));                \
            bb[ib][_nb*4+3] = __ldg((const uint32_t*)(blp + _ro + 8));            \
        }                                                                         \
    } while (0)

    // prologue: A chunks 0,1 ; B kfrags 0,1 (chunk 0)
    LOAD_A(0, 0);
    LOAD_A(1, 1);
    LOAD_B(0, 0);
    LOAD_B(1, 1);

#pragma unroll 2
    for (int c = 0; c < NCHUNK; c++) {
        const int ib = c & 1;

        // split entire A chunk -> fragment registers (frees ar[ib])
        uint32_t ah[8], al[8];
#pragma unroll
        for (int i = 0; i < 8; i++) split2(ar[ib][i].x, ar[ib][i].y, ah[i], al[i]);

        // prefetch A chunk c+2 into freed buffer
        if (c + 2 < NCHUNK) LOAD_A(c + 2, ib);

        // kfrag 0 (k 0..15 of chunk)
#pragma unroll
        for (int nb = 0; nb < 4; nb++) {
            mma16816(acc[nb], ah[0], ah[1], ah[2], ah[3], bb[0][nb*4+0], bb[0][nb*4+1]);
            mma16816(acc[nb], ah[0], ah[1], ah[2], ah[3], bb[0][nb*4+2], bb[0][nb*4+3]);
            mma16816(acc[nb], al[0], al[1], al[2], al[3], bb[0][nb*4+0], bb[0][nb*4+1]);
        }
        if (c + 1 < NCHUNK) LOAD_B(2 * (c + 1), 0);

        // kfrag 1 (k 16..31 of chunk)
#pragma unroll
        for (int nb = 0; nb < 4; nb++) {
            mma16816(acc[nb], ah[4], ah[5], ah[6], ah[7], bb[1][nb*4+0], bb[1][nb*4+1]);
            mma16816(acc[nb], ah[4], ah[5], ah[6], ah[7], bb[1][nb*4+2], bb[1][nb*4+3]);
            mma16816(acc[nb], al[4], al[5], al[6], al[7], bb[1][nb*4+0], bb[1][nb*4+1]);
        }
        if (c + 1 < NCHUNK) LOAD_B(2 * (c + 1) + 1, 1);
    }
#undef LOAD_A
#undef LOAD_B

    // ---- epilogue (per-warp, no sync needed) ----
    const int rA = row0 + wl * 16 + rsub;
#pragma unroll
    for (int nb = 0; nb < 4; nb++) {
        const int col = nb * 8 + kq;
        const size_t o0 = ((size_t)b * NN + rA) * FF + col;
        const size_t o1 = o0 + 8 * FF;
        float2 v0 = make_float2(alpha * acc[nb][0], alpha * acc[nb][1]);
        float2 v1 = make_float2(alpha * acc[nb][2], alpha * acc[nb][3]);
        if (beta != 0.0f) {
            const float2 q0 = *(const float2*)(Tpp + o0);
            const float2 q1 = *(const float2*)(Tpp + o1);
            v0.x += beta * q0.x; v0.y += beta * q0.y;
            v1.x += beta * q1.x; v1.y += beta * q1.y;
        }
        *(float2*)(Tnew + o0) = v0;
        *(float2*)(Tnew + o1) = v1;

        uint32_t h0, l0, h1, l1;
        split2(v0.x, v0.y, h0, l0);
        split2(v1.x, v1.y, h1, l1);

        const size_t p0 = ((size_t)b * NN + rA) * PK + pslot * FF + col;
        const size_t p1 = p0 + 8 * PK;
        *(uint32_t*)(outPHi + p0) = h0;
        *(uint32_t*)(outPLo + p0) = l0;
        *(uint32_t*)(outPHi + p1) = h1;
        *(uint32_t*)(outPLo + p1) = l1;

        const size_t gA = ((size_t)b * FF + col) * NN;
        ((uint16_t*)outGHi)[gA + rA]           = (uint16_t)(h0 & 0xFFFF);
        ((uint16_t*)outGHi)[gA + NN + rA]      = (uint16_t)(h0 >> 16);
        ((uint16_t*)outGLo)[gA + rA]           = (uint16_t)(l0 & 0xFFFF);
        ((uint16_t*)outGLo)[gA + NN + rA]      = (uint16_t)(l0 >> 16);
        ((uint16_t*)outGHi)[gA + rA + 8]       = (uint16_t)(h1 & 0xFFFF);
        ((uint16_t*)outGHi)[gA + NN + rA + 8]  = (uint16_t)(h1 >> 16);
        ((uint16_t*)outGLo)[gA + rA + 8]       = (uint16_t)(l1 & 0xFFFF);
        ((uint16_t*)outGLo)[gA + NN + rA + 8]  = (uint16_t)(l1 >> 16);
    }
}

// ---------------------------------------------------------------------------
// Fused projection: out[16384,128] = A[16384,192] @ W'[192,128]
// ---------------------------------------------------------------------------
#define PJ_STRIDE 100
#define PJ_SMEM (4 * 64 * PJ_STRIDE * 4)

__global__ __launch_bounds__(256, 2) void proj_mma(
    const __nv_bfloat16* __restrict__ pHi,
    const __nv_bfloat16* __restrict__ pLo,
    const __nv_bfloat16* __restrict__ wHi,
    const __nv_bfloat16* __restrict__ wLo,
    float* __restrict__ out)
{
    extern __shared__ __align__(16) char smem[];
    uint32_t* Ah = (uint32_t*)smem;
    uint32_t* Al = Ah + 64 * PJ_STRIDE;
    uint32_t* Bh = Al + 64 * PJ_STRIDE;
    uint32_t* Bl = Bh + 64 * PJ_STRIDE;
    const uint32_t sAh = smem_u32(Ah), sAl = smem_u32(Al);
    const uint32_t sBh = smem_u32(Bh), sBl = smem_u32(Bl);

    const int tid = threadIdx.x;
    const int r0 = blockIdx.x * 64;
    const int oh = blockIdx.y;

#pragma unroll
    for (int i = 0; i < 6; i++) {
        const int idx = i * 256 + tid;
        const int row = idx / 24;
        const int ch  = idx % 24;
        cp16(sAh + row * 400 + ch * 16, pHi + (size_t)(r0 + row) * PK + ch * 8);
        cp16(sAl + row * 400 + ch * 16, pLo + (size_t)(r0 + row) * PK + ch * 8);
        cp16(sBh + row * 400 + ch * 16, wHi + (size_t)(oh * 64 + row) * PK + ch * 8);
        cp16(sBl + row * 400 + ch * 16, wLo + (size_t)(oh * 64 + row) * PK + ch * 8);
    }
    CP_COMMIT();
    CP_WAIT(0);
    __syncthreads();

    const int lane = tid & 31;
    const int wid  = tid >> 5;
    const int mw   = wid & 3;
    const int ow   = wid >> 2;
    const int rsub = lane >> 2;
    const int q    = lane & 3;

    float acc[4][4];
#pragma unroll
    for (int i = 0; i < 4; i++)
#pragma unroll
        for (int j = 0; j < 4; j++) acc[i][j] = 0.0f;

#pragma unroll
    for (int ki = 0; ki < 12; ki++) {
        const int kb2 = ki * 8;
        const uint32_t* Ar = Ah + (mw * 16 + rsub) * PJ_STRIDE + kb2 + q;
        const uint32_t* Alr = Al + (mw * 16 + rsub) * PJ_STRIDE + kb2 + q;
        const uint32_t ah0 = Ar[0],  ah1 = Ar[8 * PJ_STRIDE],  ah2 = Ar[4],  ah3 = Ar[8 * PJ_STRIDE + 4];
        const uint32_t al0 = Alr[0], al1 = Alr[8 * PJ_STRIDE], al2 = Alr[4], al3 = Alr[8 * PJ_STRIDE + 4];

#pragma unroll
        for (int nb = 0; nb < 4; nb++) {
            const int ob = ow * 32 + nb * 8 + rsub;
            const uint32_t* Br = Bh + ob * PJ_STRIDE + kb2 + q;
            const uint32_t* Blr = Bl + ob * PJ_STRIDE + kb2 + q;
            const uint32_t bh0 = Br[0], bh1 = Br[4];
            const uint32_t bl0 = Blr[0], bl1 = Blr[4];

            mma16816(acc[nb], ah0, ah1, ah2, ah3, bh0, bh1);
            mma16816(acc[nb], ah0, ah1, ah2, ah3, bl0, bl1);
            mma16816(acc[nb], al0, al1, al2, al3, bh0, bh1);
        }
    }

    const int row = r0 + mw * 16 + rsub;
#pragma unroll
    for (int nb = 0; nb < 4; nb++) {
        const int col = oh * 64 + ow * 32 + nb * 8 + q * 2;
        *(float2*)(out + (size_t)row * OO + col)       = make_float2(acc[nb][0], acc[nb][1]);
        *(float2*)(out + (size_t)(row + 8) * OO + col) = make_float2(acc[nb][2], acc[nb][3]);
    }
}

// ---------------------------------------------------------------------------
// Launcher
// ---------------------------------------------------------------------------
extern "C" void kernel_launch(void* const* d_in, const int* in_sizes, int n_in,
                              void* d_out, int out_size)
{
    const float* x = nullptr;
    const float* Lm = nullptr;
    const float* W = nullptr;
    const float* theta = nullptr;
    for (int i = 0; i < n_in; i++) {
        switch (in_sizes[i]) {
            case BB * NN * FF: x = (const float*)d_in[i]; break;
            case BB * NN * NN: Lm = (const float*)d_in[i]; break;
            case KK * FF * OO: W = (const float*)d_in[i]; break;
            case KK:           theta = (const float*)d_in[i]; break;
            default: break;
        }
    }
    float* out = (float*)d_out;

    float *bufA = nullptr, *bufB = nullptr;
    __nv_bfloat16 *btgHi = nullptr, *btgLo = nullptr;
    __nv_bfloat16 *btpHi = nullptr, *btpLo = nullptr;
    __nv_bfloat16 *wtHi = nullptr, *wtLo = nullptr;
    cudaGetSymbolAddress((void**)&bufA, g_bufA);
    cudaGetSymbolAddress((void**)&bufB, g_bufB);
    cudaGetSymbolAddress((void**)&btgHi, g_btg_hi);
    cudaGetSymbolAddress((void**)&btgLo, g_btg_lo);
    cudaGetSymbolAddress((void**)&btpHi, g_btp_hi);
    cudaGetSymbolAddress((void**)&btpLo, g_btp_lo);
    cudaGetSymbolAddress((void**)&wtHi, g_wt_hi);
    cudaGetSymbolAddress((void**)&wtLo, g_wt_lo);

    __nv_bfloat16* gHi[2] = { btgHi, btgHi + (size_t)BB * FF * NN };
    __nv_bfloat16* gLo[2] = { btgLo, btgLo + (size_t)BB * FF * NN };

    cudaFuncSetAttribute(proj_mma, cudaFuncAttributeMaxDynamicSharedMemorySize, PJ_SMEM);

    const dim3 gGrid(NN / BM, BB);
    const dim3 bGrid((BB * FF * NN) / 256);
    const dim3 wGrid((PK * OO) / 256);
    const dim3 pjGrid((BB * NN) / 64, 2);

    prep_w<<<wGrid, 256>>>(W, theta, wtHi, wtLo);
    prep_b<<<bGrid, 256>>>(x, gHi[0], gLo[0], btpHi, btpLo);

    // T1 = L @ x
    cheb_gemm_tc<<<gGrid, 128>>>(Lm, gHi[0], gLo[0], x, bufA, 1.0f, 0.0f,
                                 gHi[1], gLo[1], btpHi, btpLo, 1);
    // T2 = 2 L @ T1 - x
    cheb_gemm_tc<<<gGrid, 128>>>(Lm, gHi[1], gLo[1], x, bufB, 2.0f, -1.0f,
                                 gHi[0], gLo[0], btpHi, btpLo, 2);
    // T3 = 2 L @ T2 - T1
    cheb_gemm_tc<<<gGrid, 128>>>(Lm, gHi[0], gLo[0], bufA, bufA, 2.0f, -1.0f,
                                 gHi[1], gLo[1], btpHi, btpLo, 3);
    // T4 = 2 L @ T3 - T2
    cheb_gemm_tc<<<gGrid, 128>>>(Lm, gHi[1], gLo[1], bufB, bufB, 2.0f, -1.0f,
                                 gHi[0], gLo[0], btpHi, btpLo, 4);
    // T5 = 2 L @ T4 - T3
    cheb_gemm_tc<<<gGrid, 128>>>(Lm, gHi[0], gLo[0], bufA, bufA, 2.0f, -1.0f,
                                 gHi[1], gLo[1], btpHi, btpLo, 5);

    // out = sum_k theta_k T_k W_k
    proj_mma<<<pjGrid, 256, PJ_SMEM>>>(btpHi, btpLo, wtHi, wtLo, out);
}

// round 7
// speedup vs baseline: 2.4297x; 2.4297x over previous
#include <cuda_runtime.h>
#include <cuda_bf16.h>
#include <cstdint>

#define BB 4
#define NN 4096
#define FF 32
#define KK 6
#define OO 128

// ---- GEMM tiling ----
#define BM 64                   // rows per CTA (4 warps x 16 rows)
#define KC 128                  // k per chunk (512B per L row -> long DRAM bursts)
#define NSTAGE 2
#define NCHUNK (NN / KC)        // 32
#define PK (KK * FF)            // 192

#define AROWF 132                               // A smem row stride floats (128 + 4 pad)
#define AROWB (AROWF * 4)                       // 528
#define A_BYTES (BM * AROWB)                    // 33792
#define BROWB 272                               // B smem row stride bytes (256 + 16 pad)
#define B_BYTES (FF * BROWB)                    // 8704
#define BHI_OFF A_BYTES
#define BLO_OFF (A_BYTES + B_BYTES)
#define STAGE_BYTES (A_BYTES + 2 * B_BYTES)     // 51200
#define SMEM_TOTAL (NSTAGE * STAGE_BYTES)       // 102400

// ---- scratch ----
__device__ float g_bufA[BB * NN * FF];
__device__ float g_bufB[BB * NN * FF];
__device__ __nv_bfloat16 g_btg_hi[2][BB * FF * NN];
__device__ __nv_bfloat16 g_btg_lo[2][BB * FF * NN];
__device__ __nv_bfloat16 g_btp_hi[(size_t)BB * NN * PK];
__device__ __nv_bfloat16 g_btp_lo[(size_t)BB * NN * PK];
__device__ __nv_bfloat16 g_wt_hi[OO * PK];
__device__ __nv_bfloat16 g_wt_lo[OO * PK];

__device__ __forceinline__ uint32_t smem_u32(const void* p) {
    uint32_t a;
    asm("{ .reg .u64 t; cvta.to.shared.u64 t, %1; cvt.u32.u64 %0, t; }" : "=r"(a) : "l"(p));
    return a;
}
__device__ __forceinline__ void cp16(uint32_t dst, const void* src) {
    asm volatile("cp.async.cg.shared.global [%0], [%1], 16;" :: "r"(dst), "l"(src));
}
#define CP_COMMIT() asm volatile("cp.async.commit_group;" ::: "memory")
#define CP_WAIT(n)  asm volatile("cp.async.wait_group %0;" :: "n"(n) : "memory")

__device__ __forceinline__ void split2(float x, float y, uint32_t& hi, uint32_t& lo) {
    asm("cvt.rn.bf16x2.f32 %0, %1, %2;" : "=r"(hi) : "f"(y), "f"(x));
    const float h0 = __uint_as_float(hi << 16);
    const float h1 = __uint_as_float(hi & 0xFFFF0000u);
    const float l0 = x - h0;
    const float l1 = y - h1;
    asm("cvt.rn.bf16x2.f32 %0, %1, %2;" : "=r"(lo) : "f"(l1), "f"(l0));
}

__device__ __forceinline__ void mma16816(float* c,
                                         uint32_t a0, uint32_t a1, uint32_t a2, uint32_t a3,
                                         uint32_t b0, uint32_t b1) {
    asm volatile(
        "mma.sync.aligned.m16n8k16.row.col.f32.bf16.bf16.f32 "
        "{%0,%1,%2,%3}, {%4,%5,%6,%7}, {%8,%9}, {%0,%1,%2,%3};"
        : "+f"(c[0]), "+f"(c[1]), "+f"(c[2]), "+f"(c[3])
        : "r"(a0), "r"(a1), "r"(a2), "r"(a3), "r"(b0), "r"(b1));
}

// ---------------------------------------------------------------------------
// Prep x: fp32 [b][n][f] -> btg ([b][f][n] hi/lo)  +  btp slot 0
// ---------------------------------------------------------------------------
__global__ __launch_bounds__(256) void prep_b(
    const float* __restrict__ T,
    __nv_bfloat16* __restrict__ gHi,
    __nv_bfloat16* __restrict__ gLo,
    __nv_bfloat16* __restrict__ pHi,
    __nv_bfloat16* __restrict__ pLo)
{
    const int idx = blockIdx.x * 256 + threadIdx.x;
    const int n = idx & (NN - 1);
    const int f = (idx >> 12) & (FF - 1);
    const int b = idx >> 17;
    const float a = T[((size_t)b * NN + n) * FF + f];
    const __nv_bfloat16 h = __float2bfloat16_rn(a);
    const __nv_bfloat16 l = __float2bfloat16_rn(a - __bfloat162float(h));
    gHi[idx] = h;
    gLo[idx] = l;
    const size_t pidx = ((size_t)b * NN + n) * PK + f;
    pHi[pidx] = h;
    pLo[pidx] = l;
}

// ---------------------------------------------------------------------------
// Prep W': Wt[o][k6*32+f] = theta[k6] * W[k6][f][o], bf16 hi/lo
// ---------------------------------------------------------------------------
__global__ __launch_bounds__(256) void prep_w(
    const float* __restrict__ W,
    const float* __restrict__ theta,
    __nv_bfloat16* __restrict__ wHi,
    __nv_bfloat16* __restrict__ wLo)
{
    const int idx = blockIdx.x * 256 + threadIdx.x;
    const int o  = idx & (OO - 1);
    const int kf = idx >> 7;
    const int k6 = kf >> 5;
    const float v = theta[k6] * W[(size_t)kf * OO + o];
    const __nv_bfloat16 h = __float2bfloat16_rn(v);
    const size_t w = (size_t)o * PK + kf;
    wHi[w] = h;
    wLo[w] = __float2bfloat16_rn(v - __bfloat162float(h));
}

// ---------------------------------------------------------------------------
// HMMA GEMM: Tnew = alpha * L @ Tprev + beta * Tpp, plus bf16 term export.
// KC=128 chunks: 512B per-row DRAM bursts, double-buffered smem.
// ---------------------------------------------------------------------------
__global__ __launch_bounds__(128, 2) void cheb_gemm_tc(
    const float* __restrict__ Lmat,
    const __nv_bfloat16* __restrict__ BtHi,
    const __nv_bfloat16* __restrict__ BtLo,
    const float* __restrict__ Tpp,
    float* __restrict__ Tnew,
    float alpha, float beta,
    __nv_bfloat16* __restrict__ outGHi,
    __nv_bfloat16* __restrict__ outGLo,
    __nv_bfloat16* __restrict__ outPHi,
    __nv_bfloat16* __restrict__ outPLo,
    int pslot)
{
    extern __shared__ __align__(16) char smem[];
    const uint32_t sb = smem_u32(smem);

    const int tid  = threadIdx.x;
    const int lane = tid & 31;
    const int wl   = tid >> 5;       // warp 0..3, owns rows wl*16..+15
    const int b    = blockIdx.y;
    const int row0 = blockIdx.x * BM;

    const float* Lb = Lmat + ((size_t)b * NN + row0) * NN;
    const __nv_bfloat16* bhsrc = BtHi + (size_t)b * FF * NN;
    const __nv_bfloat16* blsrc = BtLo + (size_t)b * FF * NN;

    auto issue = [&](int c) {
        const uint32_t st = sb + (uint32_t)(c & 1) * STAGE_BYTES;
        const int k0 = c * KC;
        // A: 64 rows x 512B = 2048 x 16B, 16 per thread (each warp: 1 row, 512B contiguous)
#pragma unroll
        for (int i = 0; i < 16; i++) {
            const int idx = i * 128 + tid;
            const int r = idx >> 5, g = idx & 31;
            cp16(st + r * AROWB + g * 16, Lb + (size_t)r * NN + k0 + g * 4);
        }
        // B: hi+lo, 32 f-rows x 256B each = 1024 x 16B, 8 per thread
#pragma unroll
        for (int i = 0; i < 8; i++) {
            const int idx = i * 128 + tid;
            const int sel = idx >> 9;
            const int f = (idx >> 4) & 31, g = idx & 15;
            const __nv_bfloat16* src = sel ? blsrc : bhsrc;
            cp16(st + (sel ? BLO_OFF : BHI_OFF) + f * BROWB + g * 16,
                 src + (size_t)f * NN + k0 + g * 8);
        }
    };

    // prologue: fill both stages
    issue(0); CP_COMMIT();
    issue(1); CP_COMMIT();

    float acc[4][4];
#pragma unroll
    for (int i = 0; i < 4; i++)
#pragma unroll
        for (int j = 0; j < 4; j++) acc[i][j] = 0.0f;

    const int rsub = (lane >> 2);
    const int kq   = (lane & 3) * 2;

    for (int c = 0; c < NCHUNK; c++) {
        if (c + 1 < NCHUNK) CP_WAIT(1); else CP_WAIT(0);
        __syncthreads();

        const char* st = smem + (c & 1) * STAGE_BYTES;
        const float* As = (const float*)st;

#pragma unroll
        for (int kf = 0; kf < 8; kf++) {
            const int kb = kf * 16;
            const float* Ap = As + (wl * 16 + rsub) * AROWF + kb + kq;
            const float2 p0 = *(const float2*)(Ap);
            const float2 p1 = *(const float2*)(Ap + 8 * AROWF);
            const float2 p2 = *(const float2*)(Ap + 8);
            const float2 p3 = *(const float2*)(Ap + 8 * AROWF + 8);

            uint32_t ah0, ah1, ah2, ah3, al0, al1, al2, al3;
            split2(p0.x, p0.y, ah0, al0);
            split2(p1.x, p1.y, ah1, al1);
            split2(p2.x, p2.y, ah2, al2);
            split2(p3.x, p3.y, ah3, al3);

#pragma unroll
            for (int nb = 0; nb < 4; nb++) {
                const int n = nb * 8 + rsub;
                const char* bp = st + BHI_OFF + n * BROWB + (kb + kq) * 2;
                const uint32_t bh0 = *(const uint32_t*)(bp);
                const uint32_t bh1 = *(const uint32_t*)(bp + 16);
                const uint32_t bl0 = *(const uint32_t*)(bp + (BLO_OFF - BHI_OFF));
                const uint32_t bl1 = *(const uint32_t*)(bp + (BLO_OFF - BHI_OFF) + 16);

                mma16816(acc[nb], ah0, ah1, ah2, ah3, bh0, bh1);
                mma16816(acc[nb], ah0, ah1, ah2, ah3, bl0, bl1);
                mma16816(acc[nb], al0, al1, al2, al3, bh0, bh1);
            }
        }

        __syncthreads();                      // all warps done with stage (c&1)
        if (c + 2 < NCHUNK) { issue(c + 2); CP_COMMIT(); }
    }

    // ---- epilogue: Tnew fp32 + btg [f][n] hi/lo + btp slab slot ----
    const int rA = row0 + wl * 16 + rsub;
#pragma unroll
    for (int nb = 0; nb < 4; nb++) {
        const int col = nb * 8 + kq;
        const size_t o0 = ((size_t)b * NN + rA) * FF + col;
        const size_t o1 = o0 + 8 * FF;
        float2 v0 = make_float2(alpha * acc[nb][0], alpha * acc[nb][1]);
        float2 v1 = make_float2(alpha * acc[nb][2], alpha * acc[nb][3]);
        if (beta != 0.0f) {
            const float2 q0 = *(const float2*)(Tpp + o0);
            const float2 q1 = *(const float2*)(Tpp + o1);
            v0.x += beta * q0.x; v0.y += beta * q0.y;
            v1.x += beta * q1.x; v1.y += beta * q1.y;
        }
        *(float2*)(Tnew + o0) = v0;
        *(float2*)(Tnew + o1) = v1;

        uint32_t h0, l0, h1, l1;
        split2(v0.x, v0.y, h0, l0);
        split2(v1.x, v1.y, h1, l1);

        const size_t p0 = ((size_t)b * NN + rA) * PK + pslot * FF + col;
        const size_t p1 = p0 + 8 * PK;
        *(uint32_t*)(outPHi + p0) = h0;
        *(uint32_t*)(outPLo + p0) = l0;
        *(uint32_t*)(outPHi + p1) = h1;
        *(uint32_t*)(outPLo + p1) = l1;

        const size_t gA = ((size_t)b * FF + col) * NN;
        ((uint16_t*)outGHi)[gA + rA]           = (uint16_t)(h0 & 0xFFFF);
        ((uint16_t*)outGHi)[gA + NN + rA]      = (uint16_t)(h0 >> 16);
        ((uint16_t*)outGLo)[gA + rA]           = (uint16_t)(l0 & 0xFFFF);
        ((uint16_t*)outGLo)[gA + NN + rA]      = (uint16_t)(l0 >> 16);
        ((uint16_t*)outGHi)[gA + rA + 8]       = (uint16_t)(h1 & 0xFFFF);
        ((uint16_t*)outGHi)[gA + NN + rA + 8]  = (uint16_t)(h1 >> 16);
        ((uint16_t*)outGLo)[gA + rA + 8]       = (uint16_t)(l1 & 0xFFFF);
        ((uint16_t*)outGLo)[gA + NN + rA + 8]  = (uint16_t)(l1 >> 16);
    }
}

// ---------------------------------------------------------------------------
// Fused projection: out[16384,128] = A[16384,192] @ W'[192,128]
// ---------------------------------------------------------------------------
#define PJ_STRIDE 100
#define PJ_SMEM (4 * 64 * PJ_STRIDE * 4)

__global__ __launch_bounds__(256, 2) void proj_mma(
    const __nv_bfloat16* __restrict__ pHi,
    const __nv_bfloat16* __restrict__ pLo,
    const __nv_bfloat16* __restrict__ wHi,
    const __nv_bfloat16* __restrict__ wLo,
    float* __restrict__ out)
{
    extern __shared__ __align__(16) char smem[];
    uint32_t* Ah = (uint32_t*)smem;
    uint32_t* Al = Ah + 64 * PJ_STRIDE;
    uint32_t* Bh = Al + 64 * PJ_STRIDE;
    uint32_t* Bl = Bh + 64 * PJ_STRIDE;
    const uint32_t sAh = smem_u32(Ah), sAl = smem_u32(Al);
    const uint32_t sBh = smem_u32(Bh), sBl = smem_u32(Bl);

    const int tid = threadIdx.x;
    const int r0 = blockIdx.x * 64;
    const int oh = blockIdx.y;

#pragma unroll
    for (int i = 0; i < 6; i++) {
        const int idx = i * 256 + tid;
        const int row = idx / 24;
        const int ch  = idx % 24;
        cp16(sAh + row * 400 + ch * 16, pHi + (size_t)(r0 + row) * PK + ch * 8);
        cp16(sAl + row * 400 + ch * 16, pLo + (size_t)(r0 + row) * PK + ch * 8);
        cp16(sBh + row * 400 + ch * 16, wHi + (size_t)(oh * 64 + row) * PK + ch * 8);
        cp16(sBl + row * 400 + ch * 16, wLo + (size_t)(oh * 64 + row) * PK + ch * 8);
    }
    CP_COMMIT();
    CP_WAIT(0);
    __syncthreads();

    const int lane = tid & 31;
    const int wid  = tid >> 5;
    const int mw   = wid & 3;
    const int ow   = wid >> 2;
    const int rsub = lane >> 2;
    const int q    = lane & 3;

    float acc[4][4];
#pragma unroll
    for (int i = 0; i < 4; i++)
#pragma unroll
        for (int j = 0; j < 4; j++) acc[i][j] = 0.0f;

#pragma unroll
    for (int ki = 0; ki < 12; ki++) {
        const int kb2 = ki * 8;
        const uint32_t* Ar = Ah + (mw * 16 + rsub) * PJ_STRIDE + kb2 + q;
        const uint32_t* Alr = Al + (mw * 16 + rsub) * PJ_STRIDE + kb2 + q;
        const uint32_t ah0 = Ar[0],  ah1 = Ar[8 * PJ_STRIDE],  ah2 = Ar[4],  ah3 = Ar[8 * PJ_STRIDE + 4];
        const uint32_t al0 = Alr[0], al1 = Alr[8 * PJ_STRIDE], al2 = Alr[4], al3 = Alr[8 * PJ_STRIDE + 4];

#pragma unroll
        for (int nb = 0; nb < 4; nb++) {
            const int ob = ow * 32 + nb * 8 + rsub;
            const uint32_t* Br = Bh + ob * PJ_STRIDE + kb2 + q;
            const uint32_t* Blr = Bl + ob * PJ_STRIDE + kb2 + q;
            const uint32_t bh0 = Br[0], bh1 = Br[4];
            const uint32_t bl0 = Blr[0], bl1 = Blr[4];

            mma16816(acc[nb], ah0, ah1, ah2, ah3, bh0, bh1);
            mma16816(acc[nb], ah0, ah1, ah2, ah3, bl0, bl1);
            mma16816(acc[nb], al0, al1, al2, al3, bh0, bh1);
        }
    }

    const int row = r0 + mw * 16 + rsub;
#pragma unroll
    for (int nb = 0; nb < 4; nb++) {
        const int col = oh * 64 + ow * 32 + nb * 8 + q * 2;
        *(float2*)(out + (size_t)row * OO + col)       = make_float2(acc[nb][0], acc[nb][1]);
        *(float2*)(out + (size_t)(row + 8) * OO + col) = make_float2(acc[nb][2], acc[nb][3]);
    }
}

// ---------------------------------------------------------------------------
// Launcher
// ---------------------------------------------------------------------------
extern "C" void kernel_launch(void* const* d_in, const int* in_sizes, int n_in,
                              void* d_out, int out_size)
{
    const float* x = nullptr;
    const float* Lm = nullptr;
    const float* W = nullptr;
    const float* theta = nullptr;
    for (int i = 0; i < n_in; i++) {
        switch (in_sizes[i]) {
            case BB * NN * FF: x = (const float*)d_in[i]; break;
            case BB * NN * NN: Lm = (const float*)d_in[i]; break;
            case KK * FF * OO: W = (const float*)d_in[i]; break;
            case KK:           theta = (const float*)d_in[i]; break;
            default: break;
        }
    }
    float* out = (float*)d_out;

    float *bufA = nullptr, *bufB = nullptr;
    __nv_bfloat16 *btgHi = nullptr, *btgLo = nullptr;
    __nv_bfloat16 *btpHi = nullptr, *btpLo = nullptr;
    __nv_bfloat16 *wtHi = nullptr, *wtLo = nullptr;
    cudaGetSymbolAddress((void**)&bufA, g_bufA);
    cudaGetSymbolAddress((void**)&bufB, g_bufB);
    cudaGetSymbolAddress((void**)&btgHi, g_btg_hi);
    cudaGetSymbolAddress((void**)&btgLo, g_btg_lo);
    cudaGetSymbolAddress((void**)&btpHi, g_btp_hi);
    cudaGetSymbolAddress((void**)&btpLo, g_btp_lo);
    cudaGetSymbolAddress((void**)&wtHi, g_wt_hi);
    cudaGetSymbolAddress((void**)&wtLo, g_wt_lo);

    __nv_bfloat16* gHi[2] = { btgHi, btgHi + (size_t)BB * FF * NN };
    __nv_bfloat16* gLo[2] = { btgLo, btgLo + (size_t)BB * FF * NN };

    cudaFuncSetAttribute(cheb_gemm_tc, cudaFuncAttributeMaxDynamicSharedMemorySize, SMEM_TOTAL);
    cudaFuncSetAttribute(proj_mma, cudaFuncAttributeMaxDynamicSharedMemorySize, PJ_SMEM);

    const dim3 gGrid(NN / BM, BB);
    const dim3 bGrid((BB * FF * NN) / 256);
    const dim3 wGrid((PK * OO) / 256);
    const dim3 pjGrid((BB * NN) / 64, 2);

    prep_w<<<wGrid, 256>>>(W, theta, wtHi, wtLo);
    prep_b<<<bGrid, 256>>>(x, gHi[0], gLo[0], btpHi, btpLo);

    // T1 = L @ x
    cheb_gemm_tc<<<gGrid, 128, SMEM_TOTAL>>>(Lm, gHi[0], gLo[0], x, bufA, 1.0f, 0.0f,
                                             gHi[1], gLo[1], btpHi, btpLo, 1);
    // T2 = 2 L @ T1 - x
    cheb_gemm_tc<<<gGrid, 128, SMEM_TOTAL>>>(Lm, gHi[1], gLo[1], x, bufB, 2.0f, -1.0f,
                                             gHi[0], gLo[0], btpHi, btpLo, 2);
    // T3 = 2 L @ T2 - T1
    cheb_gemm_tc<<<gGrid, 128, SMEM_TOTAL>>>(Lm, gHi[0], gLo[0], bufA, bufA, 2.0f, -1.0f,
                                             gHi[1], gLo[1], btpHi, btpLo, 3);
    // T4 = 2 L @ T3 - T2
    cheb_gemm_tc<<<gGrid, 128, SMEM_TOTAL>>>(Lm, gHi[1], gLo[1], bufB, bufB, 2.0f, -1.0f,
                                             gHi[0], gLo[0], btpHi, btpLo, 4);
    // T5 = 2 L @ T4 - T3
    cheb_gemm_tc<<<gGrid, 128, SMEM_TOTAL>>>(Lm, gHi[0], gLo[0], bufA, bufA, 2.0f, -1.0f,
                                             gHi[1], gLo[1], btpHi, btpLo, 5);

    // out = sum_k theta_k T_k W_k
    proj_mma<<<pjGrid, 256, PJ_SMEM>>>(btpHi, btpLo, wtHi, wtLo, out);
}

// round 8
// speedup vs baseline: 2.4343x; 1.0019x over previous
#include <cuda_runtime.h>
#include <cuda_bf16.h>
#include <cstdint>

#define BB 4
#define NN 4096
#define FF 32
#define KK 6
#define OO 128

// ---- GEMM tiling ----
#define BM 64                   // rows per CTA (4 warps x 16 rows)
#define KC 128                  // k per chunk (512B per L row -> long DRAM bursts)
#define NSTAGE 2
#define NCHUNK (NN / KC)        // 32
#define PK (KK * FF)            // 192

#define AROWF 132                               // A smem row stride floats (128 + 4 pad)
#define AROWB (AROWF * 4)                       // 528
#define A_BYTES (BM * AROWB)                    // 33792
#define BROWB 272                               // B smem row stride bytes (256 + 16 pad)
#define B_BYTES (FF * BROWB)                    // 8704
#define BHI_OFF A_BYTES
#define BLO_OFF (A_BYTES + B_BYTES)
#define STAGE_BYTES (A_BYTES + 2 * B_BYTES)     // 51200
#define SMEM_TOTAL (NSTAGE * STAGE_BYTES)       // 102400

// ---- scratch ----
__device__ float g_bufA[BB * NN * FF];
__device__ float g_bufB[BB * NN * FF];
__device__ __nv_bfloat16 g_btg_hi[2][BB * FF * NN];
__device__ __nv_bfloat16 g_btg_lo[2][BB * FF * NN];
__device__ __nv_bfloat16 g_btp_hi[(size_t)BB * NN * PK];
__device__ __nv_bfloat16 g_btp_lo[(size_t)BB * NN * PK];
__device__ __nv_bfloat16 g_wt_hi[OO * PK];
__device__ __nv_bfloat16 g_wt_lo[OO * PK];

__device__ __forceinline__ uint32_t smem_u32(const void* p) {
    uint32_t a;
    asm("{ .reg .u64 t; cvta.to.shared.u64 t, %1; cvt.u32.u64 %0, t; }" : "=r"(a) : "l"(p));
    return a;
}
__device__ __forceinline__ void cp16(uint32_t dst, const void* src) {
    asm volatile("cp.async.cg.shared.global [%0], [%1], 16;" :: "r"(dst), "l"(src));
}
#define CP_COMMIT() asm volatile("cp.async.commit_group;" ::: "memory")
#define CP_WAIT(n)  asm volatile("cp.async.wait_group %0;" :: "n"(n) : "memory")

__device__ __forceinline__ void split2(float x, float y, uint32_t& hi, uint32_t& lo) {
    asm("cvt.rn.bf16x2.f32 %0, %1, %2;" : "=r"(hi) : "f"(y), "f"(x));
    const float h0 = __uint_as_float(hi << 16);
    const float h1 = __uint_as_float(hi & 0xFFFF0000u);
    const float l0 = x - h0;
    const float l1 = y - h1;
    asm("cvt.rn.bf16x2.f32 %0, %1, %2;" : "=r"(lo) : "f"(l1), "f"(l0));
}

__device__ __forceinline__ void mma16816(float* c,
                                         uint32_t a0, uint32_t a1, uint32_t a2, uint32_t a3,
                                         uint32_t b0, uint32_t b1) {
    asm volatile(
        "mma.sync.aligned.m16n8k16.row.col.f32.bf16.bf16.f32 "
        "{%0,%1,%2,%3}, {%4,%5,%6,%7}, {%8,%9}, {%0,%1,%2,%3};"
        : "+f"(c[0]), "+f"(c[1]), "+f"(c[2]), "+f"(c[3])
        : "r"(a0), "r"(a1), "r"(a2), "r"(a3), "r"(b0), "r"(b1));
}

// ---------------------------------------------------------------------------
// Prep x: fp32 [b][n][f] -> btg ([b][f][n] hi/lo)  +  btp slot 0
// ---------------------------------------------------------------------------
__global__ __launch_bounds__(256) void prep_b(
    const float* __restrict__ T,
    __nv_bfloat16* __restrict__ gHi,
    __nv_bfloat16* __restrict__ gLo,
    __nv_bfloat16* __restrict__ pHi,
    __nv_bfloat16* __restrict__ pLo)
{
    const int idx = blockIdx.x * 256 + threadIdx.x;
    const int n = idx & (NN - 1);
    const int f = (idx >> 12) & (FF - 1);
    const int b = idx >> 17;
    const float a = T[((size_t)b * NN + n) * FF + f];
    const __nv_bfloat16 h = __float2bfloat16_rn(a);
    const __nv_bfloat16 l = __float2bfloat16_rn(a - __bfloat162float(h));
    gHi[idx] = h;
    gLo[idx] = l;
    const size_t pidx = ((size_t)b * NN + n) * PK + f;
    pHi[pidx] = h;
    pLo[pidx] = l;
}

// ---------------------------------------------------------------------------
// Prep W': Wt[o][k6*32+f] = theta[k6] * W[k6][f][o], bf16 hi/lo
// ---------------------------------------------------------------------------
__global__ __launch_bounds__(256) void prep_w(
    const float* __restrict__ W,
    const float* __restrict__ theta,
    __nv_bfloat16* __restrict__ wHi,
    __nv_bfloat16* __restrict__ wLo)
{
    const int idx = blockIdx.x * 256 + threadIdx.x;
    const int o  = idx & (OO - 1);
    const int kf = idx >> 7;
    const int k6 = kf >> 5;
    const float v = theta[k6] * W[(size_t)kf * OO + o];
    const __nv_bfloat16 h = __float2bfloat16_rn(v);
    const size_t w = (size_t)o * PK + kf;
    wHi[w] = h;
    wLo[w] = __float2bfloat16_rn(v - __bfloat162float(h));
}

// ---------------------------------------------------------------------------
// HMMA GEMM: Tnew = alpha * L @ Tprev + beta * Tpp, plus bf16 term export.
// KC=128 chunks: 512B per-row DRAM bursts, double-buffered smem.
// ---------------------------------------------------------------------------
__global__ __launch_bounds__(128, 2) void cheb_gemm_tc(
    const float* __restrict__ Lmat,
    const __nv_bfloat16* __restrict__ BtHi,
    const __nv_bfloat16* __restrict__ BtLo,
    const float* __restrict__ Tpp,
    float* __restrict__ Tnew,
    float alpha, float beta,
    __nv_bfloat16* __restrict__ outGHi,
    __nv_bfloat16* __restrict__ outGLo,
    __nv_bfloat16* __restrict__ outPHi,
    __nv_bfloat16* __restrict__ outPLo,
    int pslot)
{
    extern __shared__ __align__(16) char smem[];
    const uint32_t sb = smem_u32(smem);

    const int tid  = threadIdx.x;
    const int lane = tid & 31;
    const int wl   = tid >> 5;       // warp 0..3, owns rows wl*16..+15
    const int b    = blockIdx.y;
    const int row0 = blockIdx.x * BM;

    const float* Lb = Lmat + ((size_t)b * NN + row0) * NN;
    const __nv_bfloat16* bhsrc = BtHi + (size_t)b * FF * NN;
    const __nv_bfloat16* blsrc = BtLo + (size_t)b * FF * NN;

    auto issue = [&](int c) {
        const uint32_t st = sb + (uint32_t)(c & 1) * STAGE_BYTES;
        const int k0 = c * KC;
        // A: 64 rows x 512B = 2048 x 16B, 16 per thread (each warp: 1 row, 512B contiguous)
#pragma unroll
        for (int i = 0; i < 16; i++) {
            const int idx = i * 128 + tid;
            const int r = idx >> 5, g = idx & 31;
            cp16(st + r * AROWB + g * 16, Lb + (size_t)r * NN + k0 + g * 4);
        }
        // B: hi+lo, 32 f-rows x 256B each = 1024 x 16B, 8 per thread
#pragma unroll
        for (int i = 0; i < 8; i++) {
            const int idx = i * 128 + tid;
            const int sel = idx >> 9;
            const int f = (idx >> 4) & 31, g = idx & 15;
            const __nv_bfloat16* src = sel ? blsrc : bhsrc;
            cp16(st + (sel ? BLO_OFF : BHI_OFF) + f * BROWB + g * 16,
                 src + (size_t)f * NN + k0 + g * 8);
        }
    };

    // prologue: fill both stages
    issue(0); CP_COMMIT();
    issue(1); CP_COMMIT();

    float acc[4][4];
#pragma unroll
    for (int i = 0; i < 4; i++)
#pragma unroll
        for (int j = 0; j < 4; j++) acc[i][j] = 0.0f;

    const int rsub = (lane >> 2);
    const int kq   = (lane & 3) * 2;

    for (int c = 0; c < NCHUNK; c++) {
        if (c + 1 < NCHUNK) CP_WAIT(1); else CP_WAIT(0);
        __syncthreads();

        const char* st = smem + (c & 1) * STAGE_BYTES;
        const float* As = (const float*)st;

#pragma unroll
        for (int kf = 0; kf < 8; kf++) {
            const int kb = kf * 16;
            const float* Ap = As + (wl * 16 + rsub) * AROWF + kb + kq;
            const float2 p0 = *(const float2*)(Ap);
            const float2 p1 = *(const float2*)(Ap + 8 * AROWF);
            const float2 p2 = *(const float2*)(Ap + 8);
            const float2 p3 = *(const float2*)(Ap + 8 * AROWF + 8);

            uint32_t ah0, ah1, ah2, ah3, al0, al1, al2, al3;
            split2(p0.x, p0.y, ah0, al0);
            split2(p1.x, p1.y, ah1, al1);
            split2(p2.x, p2.y, ah2, al2);
            split2(p3.x, p3.y, ah3, al3);

#pragma unroll
            for (int nb = 0; nb < 4; nb++) {
                const int n = nb * 8 + rsub;
                const char* bp = st + BHI_OFF + n * BROWB + (kb + kq) * 2;
                const uint32_t bh0 = *(const uint32_t*)(bp);
                const uint32_t bh1 = *(const uint32_t*)(bp + 16);
                const uint32_t bl0 = *(const uint32_t*)(bp + (BLO_OFF - BHI_OFF));
                const uint32_t bl1 = *(const uint32_t*)(bp + (BLO_OFF - BHI_OFF) + 16);

                mma16816(acc[nb], ah0, ah1, ah2, ah3, bh0, bh1);
                mma16816(acc[nb], ah0, ah1, ah2, ah3, bl0, bl1);
                mma16816(acc[nb], al0, al1, al2, al3, bh0, bh1);
            }
        }

        __syncthreads();                      // all warps done with stage (c&1)
        if (c + 2 < NCHUNK) { issue(c + 2); CP_COMMIT(); }
    }

    // ---- epilogue: Tnew fp32 + btg [f][n] hi/lo + btp slab slot ----
    const int rA = row0 + wl * 16 + rsub;
#pragma unroll
    for (int nb = 0; nb < 4; nb++) {
        const int col = nb * 8 + kq;
        const size_t o0 = ((size_t)b * NN + rA) * FF + col;
        const size_t o1 = o0 + 8 * FF;
        float2 v0 = make_float2(alpha * acc[nb][0], alpha * acc[nb][1]);
        float2 v1 = make_float2(alpha * acc[nb][2], alpha * acc[nb][3]);
        if (beta != 0.0f) {
            const float2 q0 = *(const float2*)(Tpp + o0);
            const float2 q1 = *(const float2*)(Tpp + o1);
            v0.x += beta * q0.x; v0.y += beta * q0.y;
            v1.x += beta * q1.x; v1.y += beta * q1.y;
        }
        *(float2*)(Tnew + o0) = v0;
        *(float2*)(Tnew + o1) = v1;

        uint32_t h0, l0, h1, l1;
        split2(v0.x, v0.y, h0, l0);
        split2(v1.x, v1.y, h1, l1);

        const size_t p0 = ((size_t)b * NN + rA) * PK + pslot * FF + col;
        const size_t p1 = p0 + 8 * PK;
        *(uint32_t*)(outPHi + p0) = h0;
        *(uint32_t*)(outPLo + p0) = l0;
        *(uint32_t*)(outPHi + p1) = h1;
        *(uint32_t*)(outPLo + p1) = l1;

        const size_t gA = ((size_t)b * FF + col) * NN;
        ((uint16_t*)outGHi)[gA + rA]           = (uint16_t)(h0 & 0xFFFF);
        ((uint16_t*)outGHi)[gA + NN + rA]      = (uint16_t)(h0 >> 16);
        ((uint16_t*)outGLo)[gA + rA]           = (uint16_t)(l0 & 0xFFFF);
        ((uint16_t*)outGLo)[gA + NN + rA]      = (uint16_t)(l0 >> 16);
        ((uint16_t*)outGHi)[gA + rA + 8]       = (uint16_t)(h1 & 0xFFFF);
        ((uint16_t*)outGHi)[gA + NN + rA + 8]  = (uint16_t)(h1 >> 16);
        ((uint16_t*)outGLo)[gA + rA + 8]       = (uint16_t)(l1 & 0xFFFF);
        ((uint16_t*)outGLo)[gA + NN + rA + 8]  = (uint16_t)(l1 >> 16);
    }
}

// ---------------------------------------------------------------------------
// Fused projection: out[16384,128] = A[16384,192] @ W'[192,128]
// ---------------------------------------------------------------------------
#define PJ_STRIDE 100
#define PJ_SMEM (4 * 64 * PJ_STRIDE * 4)

__global__ __launch_bounds__(256, 2) void proj_mma(
    const __nv_bfloat16* __restrict__ pHi,
    const __nv_bfloat16* __restrict__ pLo,
    const __nv_bfloat16* __restrict__ wHi,
    const __nv_bfloat16* __restrict__ wLo,
    float* __restrict__ out)
{
    extern __shared__ __align__(16) char smem[];
    uint32_t* Ah = (uint32_t*)smem;
    uint32_t* Al = Ah + 64 * PJ_STRIDE;
    uint32_t* Bh = Al + 64 * PJ_STRIDE;
    uint32_t* Bl = Bh + 64 * PJ_STRIDE;
    const uint32_t sAh = smem_u32(Ah), sAl = smem_u32(Al);
    const uint32_t sBh = smem_u32(Bh), sBl = smem_u32(Bl);

    const int tid = threadIdx.x;
    const int r0 = blockIdx.x * 64;
    const int oh = blockIdx.y;

#pragma unroll
    for (int i = 0; i < 6; i++) {
        const int idx = i * 256 + tid;
        const int row = idx / 24;
        const int ch  = idx % 24;
        cp16(sAh + row * 400 + ch * 16, pHi + (size_t)(r0 + row) * PK + ch * 8);
        cp16(sAl + row * 400 + ch * 16, pLo + (size_t)(r0 + row) * PK + ch * 8);
        cp16(sBh + row * 400 + ch * 16, wHi + (size_t)(oh * 64 + row) * PK + ch * 8);
        cp16(sBl + row * 400 + ch * 16, wLo + (size_t)(oh * 64 + row) * PK + ch * 8);
    }
    CP_COMMIT();
    CP_WAIT(0);
    __syncthreads();

    const int lane = tid & 31;
    const int wid  = tid >> 5;
    const int mw   = wid & 3;
    const int ow   = wid >> 2;
    const int rsub = lane >> 2;
    const int q    = lane & 3;

    float acc[4][4];
#pragma unroll
    for (int i = 0; i < 4; i++)
#pragma unroll
        for (int j = 0; j < 4; j++) acc[i][j] = 0.0f;

#pragma unroll
    for (int ki = 0; ki < 12; ki++) {
        const int kb2 = ki * 8;
        const uint32_t* Ar = Ah + (mw * 16 + rsub) * PJ_STRIDE + kb2 + q;
        const uint32_t* Alr = Al + (mw * 16 + rsub) * PJ_STRIDE + kb2 + q;
        const uint32_t ah0 = Ar[0],  ah1 = Ar[8 * PJ_STRIDE],  ah2 = Ar[4],  ah3 = Ar[8 * PJ_STRIDE + 4];
        const uint32_t al0 = Alr[0], al1 = Alr[8 * PJ_STRIDE], al2 = Alr[4], al3 = Alr[8 * PJ_STRIDE + 4];

#pragma unroll
        for (int nb = 0; nb < 4; nb++) {
            const int ob = ow * 32 + nb * 8 + rsub;
            const uint32_t* Br = Bh + ob * PJ_STRIDE + kb2 + q;
            const uint32_t* Blr = Bl + ob * PJ_STRIDE + kb2 + q;
            const uint32_t bh0 = Br[0], bh1 = Br[4];
            const uint32_t bl0 = Blr[0], bl1 = Blr[4];

            mma16816(acc[nb], ah0, ah1, ah2, ah3, bh0, bh1);
            mma16816(acc[nb], ah0, ah1, ah2, ah3, bl0, bl1);
            mma16816(acc[nb], al0, al1, al2, al3, bh0, bh1);
        }
    }

    const int row = r0 + mw * 16 + rsub;
#pragma unroll
    for (int nb = 0; nb < 4; nb++) {
        const int col = oh * 64 + ow * 32 + nb * 8 + q * 2;
        *(float2*)(out + (size_t)row * OO + col)       = make_float2(acc[nb][0], acc[nb][1]);
        *(float2*)(out + (size_t)(row + 8) * OO + col) = make_float2(acc[nb][2], acc[nb][3]);
    }
}

// ---------------------------------------------------------------------------
// Launcher
// ---------------------------------------------------------------------------
extern "C" void kernel_launch(void* const* d_in, const int* in_sizes, int n_in,
                              void* d_out, int out_size)
{
    const float* x = nullptr;
    const float* Lm = nullptr;
    const float* W = nullptr;
    const float* theta = nullptr;
    for (int i = 0; i < n_in; i++) {
        switch (in_sizes[i]) {
            case BB * NN * FF: x = (const float*)d_in[i]; break;
            case BB * NN * NN: Lm = (const float*)d_in[i]; break;
            case KK * FF * OO: W = (const float*)d_in[i]; break;
            case KK:           theta = (const float*)d_in[i]; break;
            default: break;
        }
    }
    float* out = (float*)d_out;

    float *bufA = nullptr, *bufB = nullptr;
    __nv_bfloat16 *btgHi = nullptr, *btgLo = nullptr;
    __nv_bfloat16 *btpHi = nullptr, *btpLo = nullptr;
    __nv_bfloat16 *wtHi = nullptr, *wtLo = nullptr;
    cudaGetSymbolAddress((void**)&bufA, g_bufA);
    cudaGetSymbolAddress((void**)&bufB, g_bufB);
    cudaGetSymbolAddress((void**)&btgHi, g_btg_hi);
    cudaGetSymbolAddress((void**)&btgLo, g_btg_lo);
    cudaGetSymbolAddress((void**)&btpHi, g_btp_hi);
    cudaGetSymbolAddress((void**)&btpLo, g_btp_lo);
    cudaGetSymbolAddress((void**)&wtHi, g_wt_hi);
    cudaGetSymbolAddress((void**)&wtLo, g_wt_lo);

    __nv_bfloat16* gHi[2] = { btgHi, btgHi + (size_t)BB * FF * NN };
    __nv_bfloat16* gLo[2] = { btgLo, btgLo + (size_t)BB * FF * NN };

    cudaFuncSetAttribute(cheb_gemm_tc, cudaFuncAttributeMaxDynamicSharedMemorySize, SMEM_TOTAL);
    cudaFuncSetAttribute(proj_mma, cudaFuncAttributeMaxDynamicSharedMemorySize, PJ_SMEM);

    const dim3 gGrid(NN / BM, BB);
    const dim3 bGrid((BB * FF * NN) / 256);
    const dim3 wGrid((PK * OO) / 256);
    const dim3 pjGrid((BB * NN) / 64, 2);

    prep_w<<<wGrid, 256>>>(W, theta, wtHi, wtLo);
    prep_b<<<bGrid, 256>>>(x, gHi[0], gLo[0], btpHi, btpLo);

    // T1 = L @ x
    cheb_gemm_tc<<<gGrid, 128, SMEM_TOTAL>>>(Lm, gHi[0], gLo[0], x, bufA, 1.0f, 0.0f,
                                             gHi[1], gLo[1], btpHi, btpLo, 1);
    // T2 = 2 L @ T1 - x
    cheb_gemm_tc<<<gGrid, 128, SMEM_TOTAL>>>(Lm, gHi[1], gLo[1], x, bufB, 2.0f, -1.0f,
                                             gHi[0], gLo[0], btpHi, btpLo, 2);
    // T3 = 2 L @ T2 - T1
    cheb_gemm_tc<<<gGrid, 128, SMEM_TOTAL>>>(Lm, gHi[0], gLo[0], bufA, bufA, 2.0f, -1.0f,
                                             gHi[1], gLo[1], btpHi, btpLo, 3);
    // T4 = 2 L @ T3 - T2
    cheb_gemm_tc<<<gGrid, 128, SMEM_TOTAL>>>(Lm, gHi[1], gLo[1], bufB, bufB, 2.0f, -1.0f,
                                             gHi[0], gLo[0], btpHi, btpLo, 4);
    // T5 = 2 L @ T4 - T3
    cheb_gemm_tc<<<gGrid, 128, SMEM_TOTAL>>>(Lm, gHi[0], gLo[0], bufA, bufA, 2.0f, -1.0f,
                                             gHi[1], gLo[1], btpHi, btpLo, 5);

    // out = sum_k theta_k T_k W_k
    proj_mma<<<pjGrid, 256, PJ_SMEM>>>(btpHi, btpLo, wtHi, wtLo, out);
}